// round 12
// baseline (speedup 1.0000x reference)
#include <cuda_runtime.h>
#include <cstdint>

typedef unsigned long long u64;

// ---------------- f32x2 packed helpers (sm_103a) ----------------
__device__ __forceinline__ u64 pack2(float x, float y) {
    u64 r; asm("mov.b64 %0, {%1,%2};" : "=l"(r) : "f"(x), "f"(y)); return r;
}
__device__ __forceinline__ void unpack2(u64 v, float& x, float& y) {
    asm("mov.b64 {%0,%1}, %2;" : "=f"(x), "=f"(y) : "l"(v));
}
__device__ __forceinline__ u64 fma2(u64 a, u64 b, u64 c) {
    u64 d; asm("fma.rn.f32x2 %0,%1,%2,%3;" : "=l"(d) : "l"(a), "l"(b), "l"(c)); return d;
}
__device__ __forceinline__ u64 mul2(u64 a, u64 b) {
    u64 d; asm("mul.rn.f32x2 %0,%1,%2;" : "=l"(d) : "l"(a), "l"(b)); return d;
}
__device__ __forceinline__ u64 add2(u64 a, u64 b) {
    u64 d; asm("add.rn.f32x2 %0,%1,%2;" : "=l"(d) : "l"(a), "l"(b)); return d;
}

// Problem constants (B=4, C=64, H=W=256, K=7)
#define HH 256
#define WW 256
#define CC 64
#define PAD 3
#define TILE_W 32
#define TILE_H 32                    // 2 output rows per thread
#define HALO_W 38
#define HALO_H 38                    // TILE_H + 6
#define SROW 92                      // u64/row; 2*SROW=184, (184*2)%32==16 -> conflict-free half-warps
#define TILE_SZ (HALO_H * SROW)      // 3496 u64 = 27.97 KB per buffer
#define SMEM_BYTES (2 * TILE_SZ * 8) // 55936 B (double buffer)
#define NTHREADS 128
#define CH_PER_BLOCK 16
#define F4_PER_ROW 10                // float4 windows covering [gx0-4, gx0+36)
#define NPAIRS (F4_PER_ROW * HALO_H) // 380
#define LD_TRIPS 3                   // ceil(380/128)

__device__ __forceinline__ float4 ldg_f4_guard(const float* p, bool pred) {
    float4 v = make_float4(0.f, 0.f, 0.f, 0.f);
    if (pred) v = *reinterpret_cast<const float4*>(p);
    return v;
}

// Issue predicated global loads for one channel-pair tile into registers.
__device__ __forceinline__ void tile_ldg(const float* __restrict__ xa,
                                         int gx0, int gy0, int tid,
                                         float4 fa[LD_TRIPS], float4 fb[LD_TRIPS])
{
    #pragma unroll
    for (int e = 0; e < LD_TRIPS; ++e) {
        int j = tid + NTHREADS * e;
        bool valid = (j < NPAIRS);
        int row = j / F4_PER_ROW;
        int c4  = j - row * F4_PER_ROW;
        int gy  = gy0 - PAD + row;
        int gxs = gx0 - 4 + 4 * c4;
        bool inb = valid && ((unsigned)gy < (unsigned)HH) && ((unsigned)gxs < (unsigned)WW);
        const float* pa = xa + (gy << 8) + gxs;
        fa[e] = ldg_f4_guard(pa, inb);
        fb[e] = ldg_f4_guard(pa + HH * WW, inb);
    }
}

// Strip-major duplicated layout: slot tile[r*SROW + m*8 + k] holds halo column
// lc = 4k+m (m 0..9, k 0..7); lc=0 <-> global col gx0-3. Interior cols stored up to 3x.
__device__ __forceinline__ void tile_sts(u64* __restrict__ buf, int tid,
                                         const float4 fa[LD_TRIPS], const float4 fb[LD_TRIPS])
{
    #pragma unroll
    for (int e = 0; e < LD_TRIPS; ++e) {
        int j = tid + NTHREADS * e;
        if (j < NPAIRS) {
            int row = j / F4_PER_ROW;
            int c4  = j - row * F4_PER_ROW;
            int rb  = row * SROW;
            int lc0 = 4 * c4 - 1;
            float va[4] = {fa[e].x, fa[e].y, fa[e].z, fa[e].w};
            float vb[4] = {fb[e].x, fb[e].y, fb[e].z, fb[e].w};
            #pragma unroll
            for (int i = 0; i < 4; ++i) {
                int lc = lc0 + i;
                if ((unsigned)lc < (unsigned)HALO_W) {
                    u64 v = pack2(va[i], vb[i]);
                    int q  = lc >> 2;
                    int mr = lc & 3;
                    if (lc < 32)               buf[rb + mr * 8 + q]           = v;
                    if (lc >= 4 && lc < 36)    buf[rb + (mr + 4) * 8 + q - 1] = v;
                    if (lc >= 8 && mr < 2)     buf[rb + (mr + 8) * 8 + q - 2] = v;
                }
            }
        }
    }
}

// Unnormalized tap weights {t1,t4,t9} for one output pixel.
__device__ __forceinline__ void make_w(float p, float al, float be, float ga,
                                       float& t1, float& t4, float& t9)
{
    float z  = fmaf(be, p, ga);
    float sg = __fdividef(1.0f, 1.0f + __expf(-z));
    float sig = fmaxf(al * sg, 1e-4f);
    float u  = __fdividef(0.5f, sig * sig);
    t1 = __expf(-u);
    float t2 = t1 * t1;
    t4 = t2 * t2;
    float t8 = t4 * t4;
    t9 = t8 * t1;
}

__global__ void __launch_bounds__(NTHREADS, 4)
gauss_smooth_kernel(const float* __restrict__ x,
                    const float* __restrict__ persp,
                    const float* __restrict__ alpha,
                    const float* __restrict__ beta,
                    const float* __restrict__ gamma,
                    float* __restrict__ out)
{
    extern __shared__ u64 smem[];
    u64* tbuf[2] = { smem, smem + TILE_SZ };

    const int tid = threadIdx.x;
    const int tx  = tid & 7;          // column strip (4 output cols)
    const int ty  = tid >> 3;         // 0..15; thread owns output rows 2ty, 2ty+1

    const int b   = blockIdx.z >> 2;
    const int cg  = blockIdx.z & 3;
    const int c0  = cg * CH_PER_BLOCK;
    const int gx0 = blockIdx.x * TILE_W;
    const int gy0 = blockIdx.y * TILE_H;

    const int oy0 = gy0 + 2 * ty;     // first output row
    const int ocx = gx0 + tx * 4;

    // ---------------- per-pixel weights (2 rows x 4 px), unnormalized ---------
    const float al = alpha[0];
    const float be = beta[0];
    const float ga = gamma[0];

    u64 T1a[4], T4a[4], T9a[4];       // row oy0
    u64 T1b[4], T4b[4], T9b[4];       // row oy0+1
    {
        const float* pr = persp + ((size_t)b * HH * WW) + oy0 * WW + ocx;
        float4 p0 = *reinterpret_cast<const float4*>(pr);
        float4 p1 = *reinterpret_cast<const float4*>(pr + WW);
        float pa[4] = {p0.x, p0.y, p0.z, p0.w};
        float pb[4] = {p1.x, p1.y, p1.z, p1.w};
        #pragma unroll
        for (int px = 0; px < 4; ++px) {
            float t1, t4, t9;
            make_w(pa[px], al, be, ga, t1, t4, t9);
            T1a[px] = pack2(t1, t1); T4a[px] = pack2(t4, t4); T9a[px] = pack2(t9, t9);
            make_w(pb[px], al, be, ga, t1, t4, t9);
            T1b[px] = pack2(t1, t1); T4b[px] = pack2(t4, t4); T9b[px] = pack2(t9, t9);
        }
    }

    const size_t plane = (size_t)HH * WW;
    const float* xbase = x + ((size_t)(b * CC + c0)) * plane;

    // Prologue: load + stage first channel pair.
    {
        float4 fa[LD_TRIPS], fb[LD_TRIPS];
        tile_ldg(xbase, gx0, gy0, tid, fa, fb);
        tile_sts(tbuf[0], tid, fa, fb);
    }
    __syncthreads();

    // ---------------- channel-pair loop (ONE sync per iteration) ---------------
    // sts(cp) writes tbuf[(cp+1)&1], whose prior readers (compute(cp-1)) are
    // ordered by the sync at the end of iteration cp-1; prologue sync covers cp=0.
    #pragma unroll 1
    for (int cp = 0; cp < CH_PER_BLOCK / 2; ++cp) {
        float4 fa[LD_TRIPS], fb[LD_TRIPS];
        if (cp < CH_PER_BLOCK / 2 - 1) {
            tile_ldg(xbase + (size_t)(2 * cp + 2) * plane, gx0, gy0, tid, fa, fb);
        }

        const u64* cur = tbuf[cp & 1];

        // Row-iterated compute: tile rows 2ty+r, r=0..7. Row r serves
        // out0 (tap distance |r-3|, rows 0..6) and out1 (|r-4|, rows 1..7).
        u64 acc0[4], acc1[4];
        const int rbase = 2 * ty * SROW + tx;

        #pragma unroll
        for (int r = 0; r < 8; ++r) {
            const u64* rw = &cur[rbase + r * SROW];
            u64 g[10];
            #pragma unroll
            for (int m = 0; m < 10; ++m) g[m] = rw[m * 8];

            #pragma unroll
            for (int px = 0; px < 4; ++px) {
                u64 s1 = add2(g[px + 2], g[px + 4]);
                u64 s2 = add2(g[px + 1], g[px + 5]);
                u64 s3 = add2(g[px],     g[px + 6]);
                if (r < 7) {          // contributes to out0
                    u64 h = fma2(T1a[px], s1, g[px + 3]);
                    h = fma2(T4a[px], s2, h);
                    h = fma2(T9a[px], s3, h);
                    const int d0 = (r <= 3) ? (3 - r) : (r - 3);
                    if (r == 0)       acc0[px] = mul2(T9a[px], h);
                    else if (d0 == 3) acc0[px] = fma2(T9a[px], h, acc0[px]);
                    else if (d0 == 2) acc0[px] = fma2(T4a[px], h, acc0[px]);
                    else if (d0 == 1) acc0[px] = fma2(T1a[px], h, acc0[px]);
                    else              acc0[px] = add2(acc0[px], h);
                }
                if (r >= 1) {         // contributes to out1
                    u64 h = fma2(T1b[px], s1, g[px + 3]);
                    h = fma2(T4b[px], s2, h);
                    h = fma2(T9b[px], s3, h);
                    const int d1 = (r <= 4) ? (4 - r) : (r - 4);
                    if (r == 1)       acc1[px] = mul2(T9b[px], h);
                    else if (d1 == 3) acc1[px] = fma2(T9b[px], h, acc1[px]);
                    else if (d1 == 2) acc1[px] = fma2(T4b[px], h, acc1[px]);
                    else if (d1 == 1) acc1[px] = fma2(T1b[px], h, acc1[px]);
                    else              acc1[px] = add2(acc1[px], h);
                }
            }
        }

        // Normalize (recompute 1/S^2 from T1,T4,T9 - epilogue only, not hot loop).
        float a0x[4], a0y[4], a1x[4], a1y[4];
        #pragma unroll
        for (int px = 0; px < 4; ++px) {
            float t1, t4, t9, dummy;
            unpack2(T1a[px], t1, dummy);
            unpack2(T4a[px], t4, dummy);
            unpack2(T9a[px], t9, dummy);
            float S    = fmaf(2.0f, t1 + t4 + t9, 1.0f);
            float inv  = __fdividef(1.0f, S);
            float inv2 = inv * inv;
            u64 o = mul2(acc0[px], pack2(inv2, inv2));
            unpack2(o, a0x[px], a0y[px]);

            unpack2(T1b[px], t1, dummy);
            unpack2(T4b[px], t4, dummy);
            unpack2(T9b[px], t9, dummy);
            S    = fmaf(2.0f, t1 + t4 + t9, 1.0f);
            inv  = __fdividef(1.0f, S);
            inv2 = inv * inv;
            o = mul2(acc1[px], pack2(inv2, inv2));
            unpack2(o, a1x[px], a1y[px]);
        }

        const int c = c0 + 2 * cp;
        float* ob = out + ((size_t)(b * CC + c)) * plane + (oy0 << 8) + ocx;
        *reinterpret_cast<float4*>(ob)              = make_float4(a0x[0], a0x[1], a0x[2], a0x[3]);
        *reinterpret_cast<float4*>(ob + WW)         = make_float4(a1x[0], a1x[1], a1x[2], a1x[3]);
        *reinterpret_cast<float4*>(ob + plane)      = make_float4(a0y[0], a0y[1], a0y[2], a0y[3]);
        *reinterpret_cast<float4*>(ob + plane + WW) = make_float4(a1y[0], a1y[1], a1y[2], a1y[3]);

        // Uniform branch across the block -> conditional barrier is legal.
        if (cp < CH_PER_BLOCK / 2 - 1) {
            tile_sts(tbuf[(cp + 1) & 1], tid, fa, fb);
            __syncthreads();
        }
    }
}

extern "C" void kernel_launch(void* const* d_in, const int* in_sizes, int n_in,
                              void* d_out, int out_size)
{
    const float* x     = (const float*)d_in[0];
    const float* persp = (const float*)d_in[1];
    const float* alpha = (const float*)d_in[2];
    const float* beta  = (const float*)d_in[3];
    const float* gamma = (const float*)d_in[4];
    float* out = (float*)d_out;

    cudaFuncSetAttribute(gauss_smooth_kernel,
                         cudaFuncAttributeMaxDynamicSharedMemorySize, SMEM_BYTES);

    dim3 grid(WW / TILE_W, HH / TILE_H, 4 * (CC / CH_PER_BLOCK)); // (8, 8, 16)
    dim3 block(NTHREADS);
    gauss_smooth_kernel<<<grid, block, SMEM_BYTES>>>(x, persp, alpha, beta, gamma, out);
}

// round 13
// speedup vs baseline: 1.1235x; 1.1235x over previous
#include <cuda_runtime.h>
#include <cstdint>

typedef unsigned long long u64;

// ---------------- f32x2 packed helpers (sm_103a) ----------------
__device__ __forceinline__ u64 pack2(float x, float y) {
    u64 r; asm("mov.b64 %0, {%1,%2};" : "=l"(r) : "f"(x), "f"(y)); return r;
}
__device__ __forceinline__ void unpack2(u64 v, float& x, float& y) {
    asm("mov.b64 {%0,%1}, %2;" : "=f"(x), "=f"(y) : "l"(v));
}
__device__ __forceinline__ u64 fma2(u64 a, u64 b, u64 c) {
    u64 d; asm("fma.rn.f32x2 %0,%1,%2,%3;" : "=l"(d) : "l"(a), "l"(b), "l"(c)); return d;
}
__device__ __forceinline__ u64 mul2(u64 a, u64 b) {
    u64 d; asm("mul.rn.f32x2 %0,%1,%2;" : "=l"(d) : "l"(a), "l"(b)); return d;
}
__device__ __forceinline__ u64 add2(u64 a, u64 b) {
    u64 d; asm("add.rn.f32x2 %0,%1,%2;" : "=l"(d) : "l"(a), "l"(b)); return d;
}

// Problem constants (B=4, C=64, H=W=256, K=7)
#define HH 256
#define WW 256
#define CC 64
#define PAD 3
#define TILE_W 32
#define TILE_H 16
#define HALO_W 38                    // TILE_W + 6
#define HALO_H 22                    // TILE_H + 6
#define SROW 88                      // u64 per tile row (80 slots + 8 pad)
#define TILE_SZ (HALO_H * SROW)      // 1936 u64 = 15.5 KB per buffer
#define NTHREADS 128
#define CH_PER_BLOCK 16              // 8 channel-pair iterations per block
#define F4_PER_ROW 10                // float4 windows covering [gx0-4, gx0+36)
#define NPAIRS (F4_PER_ROW * HALO_H) // 220 float4-pairs per tile
#define LD_TRIPS 2                   // ceil(220/128)

__device__ __forceinline__ float4 ldg_f4_guard(const float* p, bool pred) {
    float4 v = make_float4(0.f, 0.f, 0.f, 0.f);
    if (pred) v = *reinterpret_cast<const float4*>(p);
    return v;
}

// Issue the (predicated) global loads for one channel-pair tile into registers.
// No dependent instruction follows -> LDG latency overlaps with caller's compute.
__device__ __forceinline__ void tile_ldg(const float* __restrict__ xa,
                                         int gx0, int gy0, int tid,
                                         float4 fa[LD_TRIPS], float4 fb[LD_TRIPS])
{
    #pragma unroll
    for (int e = 0; e < LD_TRIPS; ++e) {
        int j = tid + NTHREADS * e;
        bool valid = (j < NPAIRS);
        int row = j / F4_PER_ROW;                 // constant div (mul-high)
        int c4  = j - row * F4_PER_ROW;
        int gy  = gy0 - PAD + row;
        int gxs = gx0 - 4 + 4 * c4;               // float4-aligned start
        bool inb = valid && ((unsigned)gy < (unsigned)HH) && ((unsigned)gxs < (unsigned)WW);
        const float* pa = xa + (gy << 8) + gxs;
        fa[e] = ldg_f4_guard(pa, inb);
        fb[e] = ldg_f4_guard(pa + HH * WW, inb);
    }
}

// Strip-major duplicated layout: slot tile[r*SROW + m*8 + k] holds halo column
// lc = 4k+m (m 0..9, k 0..7), lc=0 <-> global col gx0-3. Interior cols stored up to 3x
// so each compute thread's 10-tap read walk (stride 8 u64) is bank-conflict-free.
__device__ __forceinline__ void tile_sts(u64* __restrict__ buf, int tid,
                                         const float4 fa[LD_TRIPS], const float4 fb[LD_TRIPS])
{
    #pragma unroll
    for (int e = 0; e < LD_TRIPS; ++e) {
        int j = tid + NTHREADS * e;
        if (j < NPAIRS) {
            int row = j / F4_PER_ROW;
            int c4  = j - row * F4_PER_ROW;
            int rb  = row * SROW;
            int lc0 = 4 * c4 - 1;
            float va[4] = {fa[e].x, fa[e].y, fa[e].z, fa[e].w};
            float vb[4] = {fb[e].x, fb[e].y, fb[e].z, fb[e].w};
            #pragma unroll
            for (int i = 0; i < 4; ++i) {
                int lc = lc0 + i;
                if ((unsigned)lc < (unsigned)HALO_W) {
                    u64 v = pack2(va[i], vb[i]);
                    int q  = lc >> 2;
                    int mr = lc & 3;
                    if (lc < 32)               buf[rb + mr * 8 + q]           = v;
                    if (lc >= 4 && lc < 36)    buf[rb + (mr + 4) * 8 + q - 1] = v;
                    if (lc >= 8 && mr < 2)     buf[rb + (mr + 8) * 8 + q - 2] = v;
                }
            }
        }
    }
}

__global__ void __launch_bounds__(NTHREADS, 5)
gauss_smooth_kernel(const float* __restrict__ x,
                    const float* __restrict__ persp,
                    const float* __restrict__ alpha,
                    const float* __restrict__ beta,
                    const float* __restrict__ gamma,
                    float* __restrict__ out)
{
    __shared__ u64 tile[2][TILE_SZ];

    const int tid = threadIdx.x;
    const int tx  = tid & 7;         // column strip (4 output cols each)
    const int ty  = tid >> 3;        // output row within tile (0..15)

    const int b   = blockIdx.z >> 2;
    const int cg  = blockIdx.z & 3;
    const int c0  = cg * CH_PER_BLOCK;
    const int gx0 = blockIdx.x * TILE_W;
    const int gy0 = blockIdx.y * TILE_H;

    const int oy  = gy0 + ty;
    const int ocx = gx0 + tx * 4;

    // ---------------- per-pixel weights (shared across all channels) ----------
    // Unnormalized tap weights {1, t1, t4, t9}; normalize once at the end by 1/S^2.
    const float al = alpha[0];
    const float be = beta[0];
    const float ga = gamma[0];

    u64 T1[4], T4[4], T9[4], INV[4];
    {
        const float* prow = persp + ((size_t)b * HH * WW) + oy * WW + ocx;
        #pragma unroll
        for (int px = 0; px < 4; ++px) {
            float p  = prow[px];
            float z  = fmaf(be, p, ga);
            float sg = __fdividef(1.0f, 1.0f + __expf(-z));
            float sig = fmaxf(al * sg, 1e-4f);
            float u  = __fdividef(0.5f, sig * sig);
            float t1 = __expf(-u);
            float t2 = t1 * t1;
            float t4 = t2 * t2;
            float t8 = t4 * t4;
            float t9 = t8 * t1;
            float S  = 1.0f + 2.0f * (t1 + t4 + t9);
            float inv = __fdividef(1.0f, S);
            float inv2 = inv * inv;
            T1[px]  = pack2(t1, t1);
            T4[px]  = pack2(t4, t4);
            T9[px]  = pack2(t9, t9);
            INV[px] = pack2(inv2, inv2);
        }
    }

    const int sbase = ty * SROW + tx;
    const size_t plane = (size_t)HH * WW;
    const float* xbase = x + ((size_t)(b * CC + c0)) * plane;

    // Prologue: load + stage first channel pair.
    {
        float4 fa[LD_TRIPS], fb[LD_TRIPS];
        tile_ldg(xbase, gx0, gy0, tid, fa, fb);
        tile_sts(tile[0], tid, fa, fb);
    }
    __syncthreads();

    // ---------------- channel-pair loop (register-pipelined loads) -------------
    // ONE sync per iteration: sts(cp) writes tile[(cp+1)&1], whose prior readers
    // (compute(cp-1)) are ordered by the sync at the end of iteration cp-1; the
    // prologue sync covers iteration 0.
    #pragma unroll 1
    for (int cp = 0; cp < CH_PER_BLOCK / 2; ++cp) {
        // Issue next tile's LDGs now; latency hidden by the compute below.
        float4 fa[LD_TRIPS], fb[LD_TRIPS];
        if (cp < CH_PER_BLOCK / 2 - 1) {
            tile_ldg(xbase + (size_t)(2 * cp + 2) * plane, gx0, gy0, tid, fa, fb);
        }

        const u64* cur = tile[cp & 1];

        // Vertical symmetry fold (d-groups: rows ty+d & ty+6-d), then
        // symmetric horizontal 7-tap {1,t1,t4,t9}, all packed f32x2.
        u64 acc[4];

        #pragma unroll
        for (int d = 0; d < 4; ++d) {
            u64 g[10];
            if (d < 3) {
                const u64* ra = &cur[sbase + d * SROW];
                const u64* rb = &cur[sbase + (6 - d) * SROW];
                #pragma unroll
                for (int m = 0; m < 10; ++m) g[m] = add2(ra[m * 8], rb[m * 8]);
            } else {
                const u64* rc = &cur[sbase + 3 * SROW];
                #pragma unroll
                for (int m = 0; m < 10; ++m) g[m] = rc[m * 8];
            }
            #pragma unroll
            for (int px = 0; px < 4; ++px) {
                u64 s1 = add2(g[px + 2], g[px + 4]);
                u64 s2 = add2(g[px + 1], g[px + 5]);
                u64 s3 = add2(g[px],     g[px + 6]);
                u64 h  = fma2(T1[px], s1, g[px + 3]);
                h      = fma2(T4[px], s2, h);
                h      = fma2(T9[px], s3, h);
                // vertical weight by d-group: d=0 -> t9, 1 -> t4, 2 -> t1, 3 -> 1
                if (d == 0)      acc[px] = mul2(T9[px], h);
                else if (d == 1) acc[px] = fma2(T4[px], h, acc[px]);
                else if (d == 2) acc[px] = fma2(T1[px], h, acc[px]);
                else             acc[px] = add2(acc[px], h);
            }
        }

        // Normalize and write out: channel c (.x) and c+1 (.y), one float4 each.
        float ax[4], ay[4];
        #pragma unroll
        for (int px = 0; px < 4; ++px) {
            u64 o = mul2(acc[px], INV[px]);
            unpack2(o, ax[px], ay[px]);
        }

        const int c = c0 + 2 * cp;
        float* ob = out + ((size_t)(b * CC + c)) * plane + (oy << 8) + ocx;
        *reinterpret_cast<float4*>(ob)         = make_float4(ax[0], ax[1], ax[2], ax[3]);
        *reinterpret_cast<float4*>(ob + plane) = make_float4(ay[0], ay[1], ay[2], ay[3]);

        // Uniform branch across the block -> conditional barrier is legal.
        if (cp < CH_PER_BLOCK / 2 - 1) {
            tile_sts(tile[(cp + 1) & 1], tid, fa, fb);
            __syncthreads();   // staged tile visible; also fences next sts vs this compute
        }
    }
}

extern "C" void kernel_launch(void* const* d_in, const int* in_sizes, int n_in,
                              void* d_out, int out_size)
{
    const float* x     = (const float*)d_in[0];
    const float* persp = (const float*)d_in[1];
    const float* alpha = (const float*)d_in[2];
    const float* beta  = (const float*)d_in[3];
    const float* gamma = (const float*)d_in[4];
    float* out = (float*)d_out;

    dim3 grid(WW / TILE_W, HH / TILE_H, 4 * (CC / CH_PER_BLOCK)); // (8, 16, 16)
    dim3 block(NTHREADS);
    gauss_smooth_kernel<<<grid, block>>>(x, persp, alpha, beta, gamma, out);
}

// round 15
// speedup vs baseline: 1.1569x; 1.0298x over previous
#include <cuda_runtime.h>
#include <cstdint>

typedef unsigned long long u64;

// ---------------- f32x2 packed helpers (sm_103a) ----------------
__device__ __forceinline__ u64 pack2(float x, float y) {
    u64 r; asm("mov.b64 %0, {%1,%2};" : "=l"(r) : "f"(x), "f"(y)); return r;
}
__device__ __forceinline__ void unpack2(u64 v, float& x, float& y) {
    asm("mov.b64 {%0,%1}, %2;" : "=f"(x), "=f"(y) : "l"(v));
}
__device__ __forceinline__ u64 fma2(u64 a, u64 b, u64 c) {
    u64 d; asm("fma.rn.f32x2 %0,%1,%2,%3;" : "=l"(d) : "l"(a), "l"(b), "l"(c)); return d;
}
__device__ __forceinline__ u64 mul2(u64 a, u64 b) {
    u64 d; asm("mul.rn.f32x2 %0,%1,%2;" : "=l"(d) : "l"(a), "l"(b)); return d;
}
__device__ __forceinline__ u64 add2(u64 a, u64 b) {
    u64 d; asm("add.rn.f32x2 %0,%1,%2;" : "=l"(d) : "l"(a), "l"(b)); return d;
}

// Problem constants (B=4, C=64, H=W=256, K=7)
#define HH 256
#define WW 256
#define CC 64
#define PAD 3
#define TILE_W 32
#define TILE_H 16
#define HALO_W 38                    // TILE_W + 6
#define HALO_H 22                    // TILE_H + 6
#define SROW 88                      // u64 per tile row (80 slots + 8 pad)
#define TILE_SZ (HALO_H * SROW)      // 1936 u64 = 15.5 KB per buffer
#define NTHREADS 128
#define CH_PER_BLOCK 16              // 8 channel-pair iterations per block
#define F4_PER_ROW 10                // float4 windows covering [gx0-4, gx0+36)
#define NPAIRS (F4_PER_ROW * HALO_H) // 220 float4-pairs per tile

__device__ __forceinline__ float4 ldg_f4_guard(const float* p, bool pred) {
    float4 v = make_float4(0.f, 0.f, 0.f, 0.f);
    if (pred) v = *reinterpret_cast<const float4*>(p);
    return v;
}

// Issue the (predicated) global loads for one channel-pair tile into registers.
// No dependent instruction follows -> LDG latency overlaps with caller's compute.
__device__ __forceinline__ void tile_ldg(const float* __restrict__ xa,
                                         int gx0, int gy0, int tid,
                                         float4 fa[2], float4 fb[2])
{
    #pragma unroll
    for (int e = 0; e < 2; ++e) {
        int j = tid + NTHREADS * e;
        bool valid = (j < NPAIRS);
        int row = j / F4_PER_ROW;                 // constant div (mul-high)
        int c4  = j - row * F4_PER_ROW;
        int gy  = gy0 - PAD + row;
        int gxs = gx0 - 4 + 4 * c4;               // float4-aligned start
        bool inb = valid && ((unsigned)gy < (unsigned)HH) && ((unsigned)gxs < (unsigned)WW);
        const float* pa = xa + (gy << 8) + gxs;
        fa[e] = ldg_f4_guard(pa, inb);
        fb[e] = ldg_f4_guard(pa + HH * WW, inb);
    }
}

// Scatter the register-held tile into the duplicated strip-major smem layout.
// Slot (m, k) holds halo column c = 4k + m (strip m in 0..9, k in 0..7);
// interior columns are stored up to 3x so compute reads are conflict-free.
__device__ __forceinline__ void tile_sts(u64* __restrict__ buf, int tid,
                                         const float4 fa[2], const float4 fb[2])
{
    #pragma unroll
    for (int e = 0; e < 2; ++e) {
        int j = tid + NTHREADS * e;
        if (j < NPAIRS) {
            int row = j / F4_PER_ROW;
            int c4  = j - row * F4_PER_ROW;
            int rb  = row * SROW;
            int lc0 = 4 * c4 - 1;                 // halo col of lane i=0
            float va[4] = {fa[e].x, fa[e].y, fa[e].z, fa[e].w};
            float vb[4] = {fb[e].x, fb[e].y, fb[e].z, fb[e].w};
            #pragma unroll
            for (int i = 0; i < 4; ++i) {
                int lc = lc0 + i;
                if ((unsigned)lc < (unsigned)HALO_W) {
                    u64 v = pack2(va[i], vb[i]);
                    int q  = lc >> 2;
                    int mr = lc & 3;
                    if (lc < 32)               buf[rb + mr * 8 + q]           = v; // m=mr,   k=q
                    if (lc >= 4 && lc < 36)    buf[rb + (mr + 4) * 8 + q - 1] = v; // m=mr+4, k=q-1
                    if (lc >= 8 && mr < 2)     buf[rb + (mr + 8) * 8 + q - 2] = v; // m=mr+8, k=q-2
                }
            }
        }
    }
}

__global__ void __launch_bounds__(NTHREADS, 5)
gauss_smooth_kernel(const float* __restrict__ x,
                    const float* __restrict__ persp,
                    const float* __restrict__ alpha,
                    const float* __restrict__ beta,
                    const float* __restrict__ gamma,
                    float* __restrict__ out)
{
    __shared__ u64 tile[2][TILE_SZ];

    const int tid = threadIdx.x;
    const int tx  = tid & 7;         // column strip (4 output cols each)
    const int ty  = tid >> 3;        // output row within tile (0..15)

    const int b   = blockIdx.z >> 2;
    const int cg  = blockIdx.z & 3;
    const int c0  = cg * CH_PER_BLOCK;
    const int gx0 = blockIdx.x * TILE_W;
    const int gy0 = blockIdx.y * TILE_H;

    const int oy  = gy0 + ty;
    const int ocx = gx0 + tx * 4;

    // ---------------- per-pixel weights (shared across all channels) ----------
    const float al = alpha[0];
    const float be = beta[0];
    const float ga = gamma[0];

    u64 W2[4][4];                    // broadcast-packed normalized weights by tap distance
    {
        const float* prow = persp + ((size_t)b * HH * WW) + oy * WW + ocx;
        #pragma unroll
        for (int px = 0; px < 4; ++px) {
            float p  = prow[px];
            float z  = fmaf(be, p, ga);
            float sg = __fdividef(1.0f, 1.0f + __expf(-z));
            float sig = fmaxf(al * sg, 1e-4f);
            float u  = __fdividef(0.5f, sig * sig);
            float t1 = __expf(-u);
            float t4 = t1 * t1; t4 = t4 * t4;          // t^4
            float t9 = t4 * t4 * t1;                    // t^9
            float S  = 1.0f + 2.0f * (t1 + t4 + t9);
            float inv = __fdividef(1.0f, S);
            float w0 = inv, w1 = t1 * inv, w2 = t4 * inv, w3 = t9 * inv;
            W2[px][0] = pack2(w0, w0);
            W2[px][1] = pack2(w1, w1);
            W2[px][2] = pack2(w2, w2);
            W2[px][3] = pack2(w3, w3);
        }
    }

    const int sbase = ty * SROW + tx;
    const size_t plane = (size_t)HH * WW;
    const float* xbase = x + ((size_t)(b * CC + c0)) * plane;

    // Prologue: load + stage first channel pair (cold start, LDG exposed once).
    {
        float4 fa[2], fb[2];
        tile_ldg(xbase, gx0, gy0, tid, fa, fb);
        tile_sts(tile[0], tid, fa, fb);
    }
    __syncthreads();

    // ---------------- channel-pair loop (register-pipelined loads) -------------
    #pragma unroll 1
    for (int cp = 0; cp < CH_PER_BLOCK / 2; ++cp) {
        // Issue next tile's LDGs now; latency hidden by the compute below.
        float4 fa[2], fb[2];
        if (cp < CH_PER_BLOCK / 2 - 1) {
            tile_ldg(xbase + (size_t)(2 * cp + 2) * plane, gx0, gy0, tid, fa, fb);
        }

        const u64* cur = tile[cp & 1];

        // Vertical symmetry fold, then horizontal 7-tap, all packed f32x2.
        u64 acc[4];
        #pragma unroll
        for (int px = 0; px < 4; ++px) acc[px] = 0ull;

        #pragma unroll
        for (int d = 0; d < 4; ++d) {
            u64 g[10];
            if (d < 3) {
                const u64* ra = &cur[sbase + d * SROW];
                const u64* rb = &cur[sbase + (6 - d) * SROW];
                #pragma unroll
                for (int m = 0; m < 10; ++m) g[m] = add2(ra[m * 8], rb[m * 8]);
            } else {
                const u64* rc = &cur[sbase + 3 * SROW];
                #pragma unroll
                for (int m = 0; m < 10; ++m) g[m] = rc[m * 8];
            }
            const int vk = (d < 3) ? (3 - d) : 0;
            #pragma unroll
            for (int px = 0; px < 4; ++px) {
                u64 h = mul2(W2[px][3], g[px]);
                h = fma2(W2[px][2], g[px + 1], h);
                h = fma2(W2[px][1], g[px + 2], h);
                h = fma2(W2[px][0], g[px + 3], h);
                h = fma2(W2[px][1], g[px + 4], h);
                h = fma2(W2[px][2], g[px + 5], h);
                h = fma2(W2[px][3], g[px + 6], h);
                acc[px] = fma2(W2[px][vk], h, acc[px]);
            }
        }

        // Write out: channel c (.x lanes) and c+1 (.y lanes), one float4 each.
        float ax[4], ay[4];
        #pragma unroll
        for (int px = 0; px < 4; ++px) unpack2(acc[px], ax[px], ay[px]);

        const int c = c0 + 2 * cp;
        float* ob = out + ((size_t)(b * CC + c)) * plane + (oy << 8) + ocx;
        *reinterpret_cast<float4*>(ob)         = make_float4(ax[0], ax[1], ax[2], ax[3]);
        *reinterpret_cast<float4*>(ob + plane) = make_float4(ay[0], ay[1], ay[2], ay[3]);

        __syncthreads();   // all reads of tile[(cp+1)&1] (from iter cp-1) complete
        if (cp < CH_PER_BLOCK / 2 - 1) {
            tile_sts(tile[(cp + 1) & 1], tid, fa, fb);
        }
        __syncthreads();   // staged tile visible before next compute
    }
}

extern "C" void kernel_launch(void* const* d_in, const int* in_sizes, int n_in,
                              void* d_out, int out_size)
{
    const float* x     = (const float*)d_in[0];
    const float* persp = (const float*)d_in[1];
    const float* alpha = (const float*)d_in[2];
    const float* beta  = (const float*)d_in[3];
    const float* gamma = (const float*)d_in[4];
    float* out = (float*)d_out;

    dim3 grid(WW / TILE_W, HH / TILE_H, 4 * (CC / CH_PER_BLOCK)); // (8, 16, 16)
    dim3 block(NTHREADS);
    gauss_smooth_kernel<<<grid, block>>>(x, persp, alpha, beta, gamma, out);
}

// round 16
// speedup vs baseline: 1.1612x; 1.0037x over previous
#include <cuda_runtime.h>
#include <cstdint>

typedef unsigned long long u64;

// ---------------- f32x2 packed helpers (sm_103a) ----------------
__device__ __forceinline__ u64 pack2(float x, float y) {
    u64 r; asm("mov.b64 %0, {%1,%2};" : "=l"(r) : "f"(x), "f"(y)); return r;
}
__device__ __forceinline__ void unpack2(u64 v, float& x, float& y) {
    asm("mov.b64 {%0,%1}, %2;" : "=f"(x), "=f"(y) : "l"(v));
}
__device__ __forceinline__ u64 fma2(u64 a, u64 b, u64 c) {
    u64 d; asm("fma.rn.f32x2 %0,%1,%2,%3;" : "=l"(d) : "l"(a), "l"(b), "l"(c)); return d;
}
__device__ __forceinline__ u64 mul2(u64 a, u64 b) {
    u64 d; asm("mul.rn.f32x2 %0,%1,%2;" : "=l"(d) : "l"(a), "l"(b)); return d;
}
__device__ __forceinline__ u64 add2(u64 a, u64 b) {
    u64 d; asm("add.rn.f32x2 %0,%1,%2;" : "=l"(d) : "l"(a), "l"(b)); return d;
}

// Problem constants (B=4, C=64, H=W=256, K=7)
#define HH 256
#define WW 256
#define CC 64
#define PAD 3
#define TILE_W 32
#define TILE_H 16
#define HALO_W 38                    // TILE_W + 6
#define HALO_H 22                    // TILE_H + 6
#define SROW 88                      // u64 per tile row (80 slots + 8 pad)
#define TILE_SZ (HALO_H * SROW)      // 1936 u64 = 15.5 KB per buffer
#define NTHREADS 128
#define CH_PER_BLOCK 16              // 8 channel-pair iterations per block
#define F4_PER_ROW 10                // float4 windows covering [gx0-4, gx0+36)
#define NPAIRS (F4_PER_ROW * HALO_H) // 220 float4-pairs per tile

__device__ __forceinline__ float4 ldg_f4_guard(const float* p, bool pred) {
    float4 v = make_float4(0.f, 0.f, 0.f, 0.f);
    if (pred) v = *reinterpret_cast<const float4*>(p);
    return v;
}

// Issue the (predicated) global loads for one channel-pair tile into registers.
// No dependent instruction follows -> LDG latency overlaps with caller's compute.
__device__ __forceinline__ void tile_ldg(const float* __restrict__ xa,
                                         int gx0, int gy0, int tid,
                                         float4 fa[2], float4 fb[2])
{
    #pragma unroll
    for (int e = 0; e < 2; ++e) {
        int j = tid + NTHREADS * e;
        bool valid = (j < NPAIRS);
        int row = j / F4_PER_ROW;                 // constant div (mul-high)
        int c4  = j - row * F4_PER_ROW;
        int gy  = gy0 - PAD + row;
        int gxs = gx0 - 4 + 4 * c4;               // float4-aligned start
        bool inb = valid && ((unsigned)gy < (unsigned)HH) && ((unsigned)gxs < (unsigned)WW);
        const float* pa = xa + (gy << 8) + gxs;
        fa[e] = ldg_f4_guard(pa, inb);
        fb[e] = ldg_f4_guard(pa + HH * WW, inb);
    }
}

// Scatter the register-held tile into the duplicated strip-major smem layout.
// Slot (m, k) holds halo column c = 4k + m (strip m in 0..9, k in 0..7);
// interior columns are stored up to 3x so compute reads are conflict-free.
__device__ __forceinline__ void tile_sts(u64* __restrict__ buf, int tid,
                                         const float4 fa[2], const float4 fb[2])
{
    #pragma unroll
    for (int e = 0; e < 2; ++e) {
        int j = tid + NTHREADS * e;
        if (j < NPAIRS) {
            int row = j / F4_PER_ROW;
            int c4  = j - row * F4_PER_ROW;
            int rb  = row * SROW;
            int lc0 = 4 * c4 - 1;                 // halo col of lane i=0
            float va[4] = {fa[e].x, fa[e].y, fa[e].z, fa[e].w};
            float vb[4] = {fb[e].x, fb[e].y, fb[e].z, fb[e].w};
            #pragma unroll
            for (int i = 0; i < 4; ++i) {
                int lc = lc0 + i;
                if ((unsigned)lc < (unsigned)HALO_W) {
                    u64 v = pack2(va[i], vb[i]);
                    int q  = lc >> 2;
                    int mr = lc & 3;
                    if (lc < 32)               buf[rb + mr * 8 + q]           = v; // m=mr,   k=q
                    if (lc >= 4 && lc < 36)    buf[rb + (mr + 4) * 8 + q - 1] = v; // m=mr+4, k=q-1
                    if (lc >= 8 && mr < 2)     buf[rb + (mr + 8) * 8 + q - 2] = v; // m=mr+8, k=q-2
                }
            }
        }
    }
}

__global__ void __launch_bounds__(NTHREADS, 5)
gauss_smooth_kernel(const float* __restrict__ x,
                    const float* __restrict__ persp,
                    const float* __restrict__ alpha,
                    const float* __restrict__ beta,
                    const float* __restrict__ gamma,
                    float* __restrict__ out)
{
    __shared__ u64 tile[2][TILE_SZ];

    const int tid = threadIdx.x;
    const int tx  = tid & 7;         // column strip (4 output cols each)
    const int ty  = tid >> 3;        // output row within tile (0..15)

    const int b   = blockIdx.z >> 2;
    const int cg  = blockIdx.z & 3;
    const int c0  = cg * CH_PER_BLOCK;
    const int gx0 = blockIdx.x * TILE_W;
    const int gy0 = blockIdx.y * TILE_H;

    const int oy  = gy0 + ty;
    const int ocx = gx0 + tx * 4;

    // ---------------- per-pixel weights (shared across all channels) ----------
    const float al = alpha[0];
    const float be = beta[0];
    const float ga = gamma[0];

    u64 W2[4][4];                    // broadcast-packed normalized weights by tap distance
    {
        const float* prow = persp + ((size_t)b * HH * WW) + oy * WW + ocx;
        #pragma unroll
        for (int px = 0; px < 4; ++px) {
            float p  = prow[px];
            float z  = fmaf(be, p, ga);
            float sg = __fdividef(1.0f, 1.0f + __expf(-z));
            float sig = fmaxf(al * sg, 1e-4f);
            float u  = __fdividef(0.5f, sig * sig);
            float t1 = __expf(-u);
            float t4 = t1 * t1; t4 = t4 * t4;          // t^4
            float t9 = t4 * t4 * t1;                    // t^9
            float S  = 1.0f + 2.0f * (t1 + t4 + t9);
            float inv = __fdividef(1.0f, S);
            float w0 = inv, w1 = t1 * inv, w2 = t4 * inv, w3 = t9 * inv;
            W2[px][0] = pack2(w0, w0);
            W2[px][1] = pack2(w1, w1);
            W2[px][2] = pack2(w2, w2);
            W2[px][3] = pack2(w3, w3);
        }
    }

    const int sbase = ty * SROW + tx;
    const size_t plane = (size_t)HH * WW;
    const float* xbase = x + ((size_t)(b * CC + c0)) * plane;

    // Prologue: load + stage first channel pair (cold start, LDG exposed once).
    {
        float4 fa[2], fb[2];
        tile_ldg(xbase, gx0, gy0, tid, fa, fb);
        tile_sts(tile[0], tid, fa, fb);
    }
    __syncthreads();

    // ---------------- channel-pair loop (register-pipelined loads) -------------
    #pragma unroll 1
    for (int cp = 0; cp < CH_PER_BLOCK / 2; ++cp) {
        // Issue next tile's LDGs now; latency hidden by the compute below.
        float4 fa[2], fb[2];
        if (cp < CH_PER_BLOCK / 2 - 1) {
            tile_ldg(xbase + (size_t)(2 * cp + 2) * plane, gx0, gy0, tid, fa, fb);
        }

        const u64* cur = tile[cp & 1];

        // Vertical symmetry fold, then horizontal 7-tap, all packed f32x2.
        u64 acc[4];
        #pragma unroll
        for (int px = 0; px < 4; ++px) acc[px] = 0ull;

        #pragma unroll
        for (int d = 0; d < 4; ++d) {
            u64 g[10];
            if (d < 3) {
                const u64* ra = &cur[sbase + d * SROW];
                const u64* rb = &cur[sbase + (6 - d) * SROW];
                #pragma unroll
                for (int m = 0; m < 10; ++m) g[m] = add2(ra[m * 8], rb[m * 8]);
            } else {
                const u64* rc = &cur[sbase + 3 * SROW];
                #pragma unroll
                for (int m = 0; m < 10; ++m) g[m] = rc[m * 8];
            }
            const int vk = (d < 3) ? (3 - d) : 0;
            #pragma unroll
            for (int px = 0; px < 4; ++px) {
                u64 h = mul2(W2[px][3], g[px]);
                h = fma2(W2[px][2], g[px + 1], h);
                h = fma2(W2[px][1], g[px + 2], h);
                h = fma2(W2[px][0], g[px + 3], h);
                h = fma2(W2[px][1], g[px + 4], h);
                h = fma2(W2[px][2], g[px + 5], h);
                h = fma2(W2[px][3], g[px + 6], h);
                acc[px] = fma2(W2[px][vk], h, acc[px]);
            }
        }

        // Write out: channel c (.x lanes) and c+1 (.y lanes), one float4 each.
        float ax[4], ay[4];
        #pragma unroll
        for (int px = 0; px < 4; ++px) unpack2(acc[px], ax[px], ay[px]);

        const int c = c0 + 2 * cp;
        float* ob = out + ((size_t)(b * CC + c)) * plane + (oy << 8) + ocx;
        *reinterpret_cast<float4*>(ob)         = make_float4(ax[0], ax[1], ax[2], ax[3]);
        *reinterpret_cast<float4*>(ob + plane) = make_float4(ay[0], ay[1], ay[2], ay[3]);

        __syncthreads();   // all reads of tile[(cp+1)&1] (from iter cp-1) complete
        if (cp < CH_PER_BLOCK / 2 - 1) {
            tile_sts(tile[(cp + 1) & 1], tid, fa, fb);
        }
        __syncthreads();   // staged tile visible before next compute
    }
}

extern "C" void kernel_launch(void* const* d_in, const int* in_sizes, int n_in,
                              void* d_out, int out_size)
{
    const float* x     = (const float*)d_in[0];
    const float* persp = (const float*)d_in[1];
    const float* alpha = (const float*)d_in[2];
    const float* beta  = (const float*)d_in[3];
    const float* gamma = (const float*)d_in[4];
    float* out = (float*)d_out;

    dim3 grid(WW / TILE_W, HH / TILE_H, 4 * (CC / CH_PER_BLOCK)); // (8, 16, 16)
    dim3 block(NTHREADS);
    gauss_smooth_kernel<<<grid, block>>>(x, persp, alpha, beta, gamma, out);
}